// round 2
// baseline (speedup 1.0000x reference)
#include <cuda_runtime.h>
#include <cstdint>

// 134 MB persistent scatter accumulator. Zero-initialized at module load;
// top_kernel re-zeroes every element after consuming it, so it is zero at
// entry of every kernel_launch call (deterministic, graph-capture safe,
// no allocations).
#define NMAX 131072
__device__ float g_agg[(size_t)NMAX * 256];

__device__ __forceinline__ uint32_t f2tf32(float x) {
    uint32_t r;
    asm("cvt.rna.tf32.f32 %0, %1;" : "=r"(r) : "f"(x));
    return r;
}

__device__ __forceinline__ void mma_tf32(float* c, const uint32_t* a, const uint32_t* b) {
    asm volatile(
        "mma.sync.aligned.m16n8k8.row.col.f32.tf32.tf32.f32 "
        "{%0,%1,%2,%3}, {%4,%5,%6,%7}, {%8,%9}, {%0,%1,%2,%3};\n"
        : "+f"(c[0]), "+f"(c[1]), "+f"(c[2]), "+f"(c[3])
        : "r"(a[0]), "r"(a[1]), "r"(a[2]), "r"(a[3]),
          "r"(b[0]), "r"(b[1]));
}

// ---------------------------------------------------------------------------
// Kernel 1: msg = (lw*h[src]) @ W_left + (rw*h[src]) @ W_right,
//           then atomicAdd rows into g_agg[edge_dest].
// Logical GEMM: [E, 512] x [512, 256], K-tiles 0..255 use W_left (scale lw),
// 256..511 use W_right (scale rw).
// ---------------------------------------------------------------------------
__global__ __launch_bounds__(256) void msg_kernel(
    const float* __restrict__ h,
    const float* __restrict__ Wl,
    const float* __restrict__ Wr,
    const int* __restrict__ esrc,
    const int* __restrict__ edest,
    const int* __restrict__ cpos,
    const int* __restrict__ ccnt,
    int E)
{
    __shared__ uint32_t As[32][129];   // [k][m] transposed, pad 129 (bank-safe)
    __shared__ uint32_t Bs[32][136];   // [k][n], pad 136 (bank-safe + 16B aligned)
    __shared__ int   s_src[128];
    __shared__ int   s_dest[128];
    __shared__ float s_lw[128];
    __shared__ float s_rw[128];

    const int tid = threadIdx.x;
    const int rm = blockIdx.x * 128;   // edge-row base
    const int n0 = blockIdx.y * 128;   // output-col base

    if (tid < 128) {
        int e = rm + tid;
        if (e < E) {
            int ci = ccnt[e];
            float cnt = (float)ci;
            float pos = (float)cpos[e];
            float denom = fmaxf(cnt - 1.0f, 1.0f);
            s_lw[tid] = (ci == 1) ? 1.0f : (cnt - 1.0f - pos) / denom;
            s_rw[tid] = (ci == 1) ? 0.0f : pos / denom;
            s_src[tid] = esrc[e];
            s_dest[tid] = edest[e];
        } else {
            s_lw[tid] = 0.0f;
            s_rw[tid] = 0.0f;
            s_src[tid] = 0;
            s_dest[tid] = -1;
        }
    }

    const int warp = tid >> 5;
    const int lane = tid & 31;
    const int wm = warp & 3;           // 4 warps along M (32 rows each)
    const int wn = warp >> 2;          // 2 warps along N (64 cols each)
    const int g = lane >> 2;           // 0..7
    const int t = lane & 3;            // 0..3

    float acc[2][8][4];
    #pragma unroll
    for (int i = 0; i < 2; i++)
        #pragma unroll
        for (int j = 0; j < 8; j++)
            #pragma unroll
            for (int k = 0; k < 4; k++)
                acc[i][j][k] = 0.0f;

    __syncthreads();

    for (int kk = 0; kk < 512; kk += 32) {
        const bool left = kk < 256;
        const int kbase = kk & 255;

        // A tile: 128 edge-rows x 32 K-cols, scaled by lw/rw, stored transposed.
        #pragma unroll
        for (int i = 0; i < 4; i++) {
            int f = tid + i * 256;        // 0..1023
            int row = f >> 3;             // 0..127
            int c4 = (f & 7) << 2;        // 0,4,..,28
            float sc = left ? s_lw[row] : s_rw[row];
            const float4 v = *reinterpret_cast<const float4*>(
                &h[(size_t)s_src[row] * 256 + kbase + c4]);
            As[c4 + 0][row] = f2tf32(v.x * sc);
            As[c4 + 1][row] = f2tf32(v.y * sc);
            As[c4 + 2][row] = f2tf32(v.z * sc);
            As[c4 + 3][row] = f2tf32(v.w * sc);
        }
        // B tile: 32 K-rows x 128 N-cols of W_left or W_right.
        const float* W = left ? Wl : Wr;
        #pragma unroll
        for (int i = 0; i < 4; i++) {
            int f = tid + i * 256;
            int row = f >> 5;             // 0..31
            int c4 = (f & 31) << 2;       // 0..124
            const float4 v = *reinterpret_cast<const float4*>(
                &W[(size_t)(kbase + row) * 256 + n0 + c4]);
            uint4 u;
            u.x = f2tf32(v.x); u.y = f2tf32(v.y);
            u.z = f2tf32(v.z); u.w = f2tf32(v.w);
            *reinterpret_cast<uint4*>(&Bs[row][c4]) = u;
        }
        __syncthreads();

        #pragma unroll
        for (int ks = 0; ks < 32; ks += 8) {
            uint32_t afr[2][4];
            #pragma unroll
            for (int mt = 0; mt < 2; mt++) {
                int mrow = wm * 32 + mt * 16 + g;
                afr[mt][0] = As[ks + t][mrow];
                afr[mt][1] = As[ks + t][mrow + 8];
                afr[mt][2] = As[ks + t + 4][mrow];
                afr[mt][3] = As[ks + t + 4][mrow + 8];
            }
            uint32_t bfr[8][2];
            #pragma unroll
            for (int nt = 0; nt < 8; nt++) {
                int ncol = wn * 64 + nt * 8 + g;
                bfr[nt][0] = Bs[ks + t][ncol];
                bfr[nt][1] = Bs[ks + t + 4][ncol];
            }
            #pragma unroll
            for (int mt = 0; mt < 2; mt++)
                #pragma unroll
                for (int nt = 0; nt < 8; nt++)
                    mma_tf32(acc[mt][nt], afr[mt], bfr[nt]);
        }
        __syncthreads();
    }

    // Epilogue: scatter-add msg rows into g_agg[dest].
    #pragma unroll
    for (int mt = 0; mt < 2; mt++) {
        int mloc = wm * 32 + mt * 16 + g;
        int d0 = s_dest[mloc];
        int d1 = s_dest[mloc + 8];
        #pragma unroll
        for (int nt = 0; nt < 8; nt++) {
            int col = n0 + wn * 64 + nt * 8 + 2 * t;
            if (d0 >= 0) {
                atomicAdd(&g_agg[(size_t)d0 * 256 + col],     acc[mt][nt][0]);
                atomicAdd(&g_agg[(size_t)d0 * 256 + col + 1], acc[mt][nt][1]);
            }
            if (d1 >= 0) {
                atomicAdd(&g_agg[(size_t)d1 * 256 + col],     acc[mt][nt][2]);
                atomicAdd(&g_agg[(size_t)d1 * 256 + col + 1], acc[mt][nt][3]);
            }
        }
    }
}

// ---------------------------------------------------------------------------
// Kernel 2: out = relu(h @ W_top + b + g_agg); zero g_agg after reading so the
// accumulator is clean for the next kernel_launch call.
// ---------------------------------------------------------------------------
__global__ __launch_bounds__(256) void top_kernel(
    const float* __restrict__ h,
    const float* __restrict__ Wt,
    const float* __restrict__ b,
    float* __restrict__ out,
    int n)
{
    __shared__ uint32_t As[32][129];
    __shared__ uint32_t Bs[32][136];

    const int tid = threadIdx.x;
    const int rm = blockIdx.x * 128;
    const int n0 = blockIdx.y * 128;

    const int warp = tid >> 5;
    const int lane = tid & 31;
    const int wm = warp & 3;
    const int wn = warp >> 2;
    const int g = lane >> 2;
    const int t = lane & 3;

    float acc[2][8][4];
    #pragma unroll
    for (int i = 0; i < 2; i++)
        #pragma unroll
        for (int j = 0; j < 8; j++)
            #pragma unroll
            for (int k = 0; k < 4; k++)
                acc[i][j][k] = 0.0f;

    for (int kk = 0; kk < 256; kk += 32) {
        #pragma unroll
        for (int i = 0; i < 4; i++) {
            int f = tid + i * 256;
            int row = f >> 3;
            int c4 = (f & 7) << 2;
            int grow = rm + row;
            if (grow >= n) grow = n - 1;   // safety clamp (exact fit in practice)
            const float4 v = *reinterpret_cast<const float4*>(
                &h[(size_t)grow * 256 + kk + c4]);
            As[c4 + 0][row] = f2tf32(v.x);
            As[c4 + 1][row] = f2tf32(v.y);
            As[c4 + 2][row] = f2tf32(v.z);
            As[c4 + 3][row] = f2tf32(v.w);
        }
        #pragma unroll
        for (int i = 0; i < 4; i++) {
            int f = tid + i * 256;
            int row = f >> 5;
            int c4 = (f & 31) << 2;
            const float4 v = *reinterpret_cast<const float4*>(
                &Wt[(size_t)(kk + row) * 256 + n0 + c4]);
            uint4 u;
            u.x = f2tf32(v.x); u.y = f2tf32(v.y);
            u.z = f2tf32(v.z); u.w = f2tf32(v.w);
            *reinterpret_cast<uint4*>(&Bs[row][c4]) = u;
        }
        __syncthreads();

        #pragma unroll
        for (int ks = 0; ks < 32; ks += 8) {
            uint32_t afr[2][4];
            #pragma unroll
            for (int mt = 0; mt < 2; mt++) {
                int mrow = wm * 32 + mt * 16 + g;
                afr[mt][0] = As[ks + t][mrow];
                afr[mt][1] = As[ks + t][mrow + 8];
                afr[mt][2] = As[ks + t + 4][mrow];
                afr[mt][3] = As[ks + t + 4][mrow + 8];
            }
            uint32_t bfr[8][2];
            #pragma unroll
            for (int nt = 0; nt < 8; nt++) {
                int ncol = wn * 64 + nt * 8 + g;
                bfr[nt][0] = Bs[ks + t][ncol];
                bfr[nt][1] = Bs[ks + t + 4][ncol];
            }
            #pragma unroll
            for (int mt = 0; mt < 2; mt++)
                #pragma unroll
                for (int nt = 0; nt < 8; nt++)
                    mma_tf32(acc[mt][nt], afr[mt], bfr[nt]);
        }
        __syncthreads();
    }

    // Fused epilogue: + g_agg + bias, ReLU, store out, zero g_agg.
    #pragma unroll
    for (int mt = 0; mt < 2; mt++) {
        int r0 = rm + wm * 32 + mt * 16 + g;
        int r1 = r0 + 8;
        #pragma unroll
        for (int nt = 0; nt < 8; nt++) {
            int col = n0 + wn * 64 + nt * 8 + 2 * t;
            float bx = b[col];
            float by = b[col + 1];
            if (r0 < n) {
                size_t i0 = (size_t)r0 * 256 + col;
                float2 a0 = *reinterpret_cast<float2*>(&g_agg[i0]);
                float2 o0;
                o0.x = fmaxf(acc[mt][nt][0] + a0.x + bx, 0.0f);
                o0.y = fmaxf(acc[mt][nt][1] + a0.y + by, 0.0f);
                *reinterpret_cast<float2*>(&out[i0]) = o0;
                *reinterpret_cast<float2*>(&g_agg[i0]) = make_float2(0.0f, 0.0f);
            }
            if (r1 < n) {
                size_t i1 = (size_t)r1 * 256 + col;
                float2 a1 = *reinterpret_cast<float2*>(&g_agg[i1]);
                float2 o1;
                o1.x = fmaxf(acc[mt][nt][2] + a1.x + bx, 0.0f);
                o1.y = fmaxf(acc[mt][nt][3] + a1.y + by, 0.0f);
                *reinterpret_cast<float2*>(&out[i1]) = o1;
                *reinterpret_cast<float2*>(&g_agg[i1]) = make_float2(0.0f, 0.0f);
            }
        }
    }
}

extern "C" void kernel_launch(void* const* d_in, const int* in_sizes, int n_in,
                              void* d_out, int out_size)
{
    const float* h   = (const float*)d_in[0];
    const float* Wl  = (const float*)d_in[1];
    const float* Wr  = (const float*)d_in[2];
    const float* Wt  = (const float*)d_in[3];
    const float* b   = (const float*)d_in[4];
    const int* esrc  = (const int*)d_in[5];
    const int* edest = (const int*)d_in[6];
    const int* cpos  = (const int*)d_in[7];
    const int* ccnt  = (const int*)d_in[8];

    const int n = in_sizes[0] / 256;   // 131072
    const int E = in_sizes[5];         // 131071

    dim3 g1((E + 127) / 128, 2);
    dim3 g2((n + 127) / 128, 2);
    msg_kernel<<<g1, 256>>>(h, Wl, Wr, esrc, edest, cpos, ccnt, E);
    top_kernel<<<g2, 256>>>(h, Wt, b, (float*)d_out, n);
}

// round 4
// speedup vs baseline: 1.3175x; 1.3175x over previous
#include <cuda_runtime.h>
#include <cstdint>

// ---------------------------------------------------------------------------
// Persistent device scratch. g_agg is zero at entry of every kernel_launch
// call (top_kernel re-zeroes after consuming). g_W holds tf32-rounded copies
// of Wl / Wr / Wt (natural [k][n] layout), rewritten every call by prep_kernel.
// ---------------------------------------------------------------------------
#define NMAX 131072
__device__ float g_agg[(size_t)NMAX * 256];
__device__ float g_W[3 * 256 * 256];

__device__ __forceinline__ uint32_t f2tf32(float x) {
    uint32_t r;
    asm("cvt.rna.tf32.f32 %0, %1;" : "=r"(r) : "f"(x));
    return r;
}

__device__ __forceinline__ uint32_t smem_u32(const void* p) {
    uint32_t a;
    asm("{ .reg .u64 t; cvta.to.shared.u64 t, %1; cvt.u32.u64 %0, t; }" : "=r"(a) : "l"(p));
    return a;
}

__device__ __forceinline__ void mma_tf32(float* c, const uint32_t* a, const uint32_t* b) {
    asm volatile(
        "mma.sync.aligned.m16n8k8.row.col.f32.tf32.tf32.f32 "
        "{%0,%1,%2,%3}, {%4,%5,%6,%7}, {%8,%9}, {%0,%1,%2,%3};\n"
        : "+f"(c[0]), "+f"(c[1]), "+f"(c[2]), "+f"(c[3])
        : "r"(a[0]), "r"(a[1]), "r"(a[2]), "r"(a[3]),
          "r"(b[0]), "r"(b[1]));
}

__device__ __forceinline__ void cp16(uint32_t dst, const void* src) {
    asm volatile("cp.async.cg.shared.global [%0], [%1], 16;" :: "r"(dst), "l"(src));
}
#define CP_COMMIT() asm volatile("cp.async.commit_group;" ::: "memory")
#define CP_WAIT0()  asm volatile("cp.async.wait_group 0;" ::: "memory")

__device__ __forceinline__ void red_add_v2(float* p, float x, float y) {
    asm volatile("red.global.add.v2.f32 [%0], {%1,%2};" :: "l"(p), "f"(x), "f"(y) : "memory");
}

// ---------------------------------------------------------------------------
// Shared-memory tile geometry (both GEMM kernels).
//   As: [32][137] u32  (K-major, transposed; 137%32==9 -> STS banks 9*c4+row
//       cover 0..31 exactly (conflict-free), frag LDS ~1.1-way)
//   Bs: [32][264] u32  (264%32==8 -> frag banks 8t+g all distinct; row stride
//       1056B keeps cp.async dst 16B-aligned)
// ---------------------------------------------------------------------------
#define AP 137
#define BP 264
#define ASZ (32 * AP * 4)
#define BSZ (32 * BP * 4)
#define STAGE (ASZ + BSZ)

// ---------------------------------------------------------------------------
// prep: g_W[m] = rna_tf32(W[m]) elementwise, m in {Wl, Wr, Wt}.
// ---------------------------------------------------------------------------
__global__ void prep_kernel(const float* __restrict__ Wl,
                            const float* __restrict__ Wr,
                            const float* __restrict__ Wt)
{
    int i = blockIdx.x * 256 + threadIdx.x;          // 0 .. 196607
    const float* src = (i < 65536) ? Wl : (i < 131072) ? Wr : Wt;
    g_W[i] = __uint_as_float(f2tf32(src[i & 65535]));
}

// ---------------------------------------------------------------------------
// msg kernel: logical GEMM [E,512] x [512,256]; K chunks 0-7 use lw-scaled h
// against Wl, 8-15 use rw-scaled h against Wr. Epilogue red.adds each msg row
// into g_agg[edge_dest]. Block tile 128x256, 8 warps, warp tile 64x64,
// cp.async double-buffered.
// ---------------------------------------------------------------------------
__global__ __launch_bounds__(256, 1) void msg_kernel(
    const float* __restrict__ h,
    const int* __restrict__ esrc,
    const int* __restrict__ edest,
    const int* __restrict__ cpos,
    const int* __restrict__ ccnt,
    int E)
{
    extern __shared__ char smem[];
    float* s_lw  = (float*)(smem);
    float* s_rw  = (float*)(smem + 512);
    int*   s_src = (int*)  (smem + 1024);
    int*   s_dst = (int*)  (smem + 1536);
    char*  tiles = smem + 2048;
    const uint32_t tiles_u32 = smem_u32(tiles);

    const int tid = threadIdx.x;
    const int rm  = blockIdx.x * 128;

    if (tid < 128) {
        int e = rm + tid;
        if (e < E) {
            int ci = ccnt[e];
            float cnt = (float)ci, pos = (float)cpos[e];
            float den = fmaxf(cnt - 1.0f, 1.0f);
            s_lw[tid] = (ci == 1) ? 1.0f : (cnt - 1.0f - pos) / den;
            s_rw[tid] = (ci == 1) ? 0.0f : pos / den;
            s_src[tid] = esrc[e];
            s_dst[tid] = edest[e];
        } else {
            s_lw[tid] = 0.0f; s_rw[tid] = 0.0f; s_src[tid] = 0; s_dst[tid] = -1;
        }
    }
    __syncthreads();

    const int wid = tid >> 5, lane = tid & 31;
    const int wm = wid >> 2, wn = wid & 3;     // 2 x 4 warp grid, 64x64 tiles
    const int g = lane >> 2, t = lane & 3;

    float acc[4][8][4];
    #pragma unroll
    for (int i = 0; i < 4; i++)
        #pragma unroll
        for (int j = 0; j < 8; j++)
            #pragma unroll
            for (int k = 0; k < 4; k++) acc[i][j][k] = 0.0f;

    float4 va[4];
    float  vsc[4];

    auto ldgA = [&](int kc) {
        const int kb = (kc & 7) * 32;
        const bool left = kc < 8;
        #pragma unroll
        for (int i = 0; i < 4; i++) {
            int f = tid + i * 256;
            int row = f >> 3, c4 = (f & 7) << 2;
            va[i] = *reinterpret_cast<const float4*>(
                &h[(size_t)s_src[row] * 256 + kb + c4]);
            vsc[i] = left ? s_lw[row] : s_rw[row];
        }
    };
    auto stsA = [&](int s) {
        uint32_t* As = (uint32_t*)(tiles + s * STAGE);
        #pragma unroll
        for (int i = 0; i < 4; i++) {
            int f = tid + i * 256;
            int row = f >> 3, c4 = (f & 7) << 2;
            float sc = vsc[i];
            As[(c4 + 0) * AP + row] = f2tf32(va[i].x * sc);
            As[(c4 + 1) * AP + row] = f2tf32(va[i].y * sc);
            As[(c4 + 2) * AP + row] = f2tf32(va[i].z * sc);
            As[(c4 + 3) * AP + row] = f2tf32(va[i].w * sc);
        }
    };
    auto cpB = [&](int kc, int s) {
        const int kb = (kc & 7) * 32;
        const float* W = g_W + ((kc < 8) ? 0 : 65536);
        uint32_t dstb = tiles_u32 + s * STAGE + ASZ;
        #pragma unroll
        for (int i = 0; i < 8; i++) {
            int f = tid + i * 256;          // 0..2047 float4 slots
            int kr = f >> 6, c4 = (f & 63) << 2;
            cp16(dstb + (uint32_t)(kr * BP + c4) * 4,
                 &W[(size_t)(kb + kr) * 256 + c4]);
        }
        CP_COMMIT();
    };
    auto compute = [&](int s) {
        const uint32_t* As = (const uint32_t*)(tiles + s * STAGE);
        const uint32_t* Bs = (const uint32_t*)(tiles + s * STAGE + ASZ);
        #pragma unroll
        for (int ks = 0; ks < 4; ks++) {
            const int k0 = ks * 8;
            uint32_t a[4][4];
            #pragma unroll
            for (int mt = 0; mt < 4; mt++) {
                int m = wm * 64 + mt * 16 + g;
                a[mt][0] = As[(k0 + t) * AP + m];
                a[mt][1] = As[(k0 + t) * AP + m + 8];
                a[mt][2] = As[(k0 + t + 4) * AP + m];
                a[mt][3] = As[(k0 + t + 4) * AP + m + 8];
            }
            uint32_t b[8][2];
            #pragma unroll
            for (int nt = 0; nt < 8; nt++) {
                int nc = wn * 64 + nt * 8 + g;
                b[nt][0] = Bs[(k0 + t) * BP + nc];
                b[nt][1] = Bs[(k0 + t + 4) * BP + nc];
            }
            #pragma unroll
            for (int mt = 0; mt < 4; mt++)
                #pragma unroll
                for (int nt = 0; nt < 8; nt++)
                    mma_tf32(acc[mt][nt], a[mt], b[nt]);
        }
    };

    // prologue
    ldgA(0); stsA(0); cpB(0, 0);
    CP_WAIT0();
    __syncthreads();

    for (int kc = 0; kc < 16; kc++) {
        const int s = kc & 1;
        if (kc + 1 < 16) { ldgA(kc + 1); cpB(kc + 1, s ^ 1); }
        compute(s);
        if (kc + 1 < 16) stsA(s ^ 1);
        CP_WAIT0();
        __syncthreads();
    }

    // epilogue: scatter-add into g_agg
    #pragma unroll
    for (int mt = 0; mt < 4; mt++) {
        int r0 = wm * 64 + mt * 16 + g;
        int d0 = s_dst[r0], d1 = s_dst[r0 + 8];
        #pragma unroll
        for (int nt = 0; nt < 8; nt++) {
            int col = wn * 64 + nt * 8 + 2 * t;
            if (d0 >= 0)
                red_add_v2(&g_agg[(size_t)d0 * 256 + col], acc[mt][nt][0], acc[mt][nt][1]);
            if (d1 >= 0)
                red_add_v2(&g_agg[(size_t)d1 * 256 + col], acc[mt][nt][2], acc[mt][nt][3]);
        }
    }
}

// ---------------------------------------------------------------------------
// top kernel: D = h @ Wt (same GEMM skeleton, NK=8, no scaling);
// epilogue out = relu(D + g_agg + b), then zeroes g_agg.
// ---------------------------------------------------------------------------
__global__ __launch_bounds__(256, 1) void top_kernel(
    const float* __restrict__ h,
    const float* __restrict__ b,
    float* __restrict__ out)
{
    extern __shared__ char smem[];
    float* s_bias = (float*)(smem);
    char*  tiles = smem + 1024;
    const uint32_t tiles_u32 = smem_u32(tiles);

    const int tid = threadIdx.x;
    const int rm  = blockIdx.x * 128;

    s_bias[tid] = b[tid];
    __syncthreads();

    const int wid = tid >> 5, lane = tid & 31;
    const int wm = wid >> 2, wn = wid & 3;
    const int g = lane >> 2, t = lane & 3;

    float acc[4][8][4];
    #pragma unroll
    for (int i = 0; i < 4; i++)
        #pragma unroll
        for (int j = 0; j < 8; j++)
            #pragma unroll
            for (int k = 0; k < 4; k++) acc[i][j][k] = 0.0f;

    float4 va[4];

    auto ldgA = [&](int kc) {
        const int kb = kc * 32;
        #pragma unroll
        for (int i = 0; i < 4; i++) {
            int f = tid + i * 256;
            int row = f >> 3, c4 = (f & 7) << 2;
            va[i] = *reinterpret_cast<const float4*>(
                &h[(size_t)(rm + row) * 256 + kb + c4]);
        }
    };
    auto stsA = [&](int s) {
        uint32_t* As = (uint32_t*)(tiles + s * STAGE);
        #pragma unroll
        for (int i = 0; i < 4; i++) {
            int f = tid + i * 256;
            int row = f >> 3, c4 = (f & 7) << 2;
            As[(c4 + 0) * AP + row] = f2tf32(va[i].x);
            As[(c4 + 1) * AP + row] = f2tf32(va[i].y);
            As[(c4 + 2) * AP + row] = f2tf32(va[i].z);
            As[(c4 + 3) * AP + row] = f2tf32(va[i].w);
        }
    };
    auto cpB = [&](int kc, int s) {
        const int kb = kc * 32;
        const float* W = g_W + 2 * 65536;
        uint32_t dstb = tiles_u32 + s * STAGE + ASZ;
        #pragma unroll
        for (int i = 0; i < 8; i++) {
            int f = tid + i * 256;
            int kr = f >> 6, c4 = (f & 63) << 2;
            cp16(dstb + (uint32_t)(kr * BP + c4) * 4,
                 &W[(size_t)(kb + kr) * 256 + c4]);
        }
        CP_COMMIT();
    };
    auto compute = [&](int s) {
        const uint32_t* As = (const uint32_t*)(tiles + s * STAGE);
        const uint32_t* Bs = (const uint32_t*)(tiles + s * STAGE + ASZ);
        #pragma unroll
        for (int ks = 0; ks < 4; ks++) {
            const int k0 = ks * 8;
            uint32_t a[4][4];
            #pragma unroll
            for (int mt = 0; mt < 4; mt++) {
                int m = wm * 64 + mt * 16 + g;
                a[mt][0] = As[(k0 + t) * AP + m];
                a[mt][1] = As[(k0 + t) * AP + m + 8];
                a[mt][2] = As[(k0 + t + 4) * AP + m];
                a[mt][3] = As[(k0 + t + 4) * AP + m + 8];
            }
            uint32_t b2[8][2];
            #pragma unroll
            for (int nt = 0; nt < 8; nt++) {
                int nc = wn * 64 + nt * 8 + g;
                b2[nt][0] = Bs[(k0 + t) * BP + nc];
                b2[nt][1] = Bs[(k0 + t + 4) * BP + nc];
            }
            #pragma unroll
            for (int mt = 0; mt < 4; mt++)
                #pragma unroll
                for (int nt = 0; nt < 8; nt++)
                    mma_tf32(acc[mt][nt], a[mt], b2[nt]);
        }
    };

    ldgA(0); stsA(0); cpB(0, 0);
    CP_WAIT0();
    __syncthreads();

    for (int kc = 0; kc < 8; kc++) {
        const int s = kc & 1;
        if (kc + 1 < 8) { ldgA(kc + 1); cpB(kc + 1, s ^ 1); }
        compute(s);
        if (kc + 1 < 8) stsA(s ^ 1);
        CP_WAIT0();
        __syncthreads();
    }

    // epilogue: out = relu(acc + g_agg + bias); g_agg = 0
    #pragma unroll
    for (int mt = 0; mt < 4; mt++) {
        int r0 = rm + wm * 64 + mt * 16 + g;
        #pragma unroll
        for (int nt = 0; nt < 8; nt++) {
            int col = wn * 64 + nt * 8 + 2 * t;
            float bx = s_bias[col], by = s_bias[col + 1];
            {
                size_t i0 = (size_t)r0 * 256 + col;
                float2 a0 = *reinterpret_cast<float2*>(&g_agg[i0]);
                float2 o;
                o.x = fmaxf(acc[mt][nt][0] + a0.x + bx, 0.0f);
                o.y = fmaxf(acc[mt][nt][1] + a0.y + by, 0.0f);
                *reinterpret_cast<float2*>(&out[i0]) = o;
                *reinterpret_cast<float2*>(&g_agg[i0]) = make_float2(0.f, 0.f);
            }
            {
                size_t i1 = (size_t)(r0 + 8) * 256 + col;
                float2 a1 = *reinterpret_cast<float2*>(&g_agg[i1]);
                float2 o;
                o.x = fmaxf(acc[mt][nt][2] + a1.x + bx, 0.0f);
                o.y = fmaxf(acc[mt][nt][3] + a1.y + by, 0.0f);
                *reinterpret_cast<float2*>(&out[i1]) = o;
                *reinterpret_cast<float2*>(&g_agg[i1]) = make_float2(0.f, 0.f);
            }
        }
    }
}

// ---------------------------------------------------------------------------
#define MSG_SMEM (2048 + 2 * STAGE)
#define TOP_SMEM (1024 + 2 * STAGE)

extern "C" void kernel_launch(void* const* d_in, const int* in_sizes, int n_in,
                              void* d_out, int out_size)
{
    const float* h   = (const float*)d_in[0];
    const float* Wl  = (const float*)d_in[1];
    const float* Wr  = (const float*)d_in[2];
    const float* Wt  = (const float*)d_in[3];
    const float* b   = (const float*)d_in[4];
    const int* esrc  = (const int*)d_in[5];
    const int* edest = (const int*)d_in[6];
    const int* cpos  = (const int*)d_in[7];
    const int* ccnt  = (const int*)d_in[8];

    const int n = in_sizes[0] / 256;   // 131072
    const int E = in_sizes[5];         // 131071

    static int cfg_done = 0;
    if (!cfg_done) {
        cudaFuncSetAttribute(msg_kernel, cudaFuncAttributeMaxDynamicSharedMemorySize, MSG_SMEM);
        cudaFuncSetAttribute(top_kernel, cudaFuncAttributeMaxDynamicSharedMemorySize, TOP_SMEM);
        cfg_done = 1;
    }

    prep_kernel<<<768, 256>>>(Wl, Wr, Wt);
    msg_kernel<<<(E + 127) / 128, 256, MSG_SMEM>>>(h, esrc, edest, cpos, ccnt, E);
    top_kernel<<<n / 128, 256, TOP_SMEM>>>(h, b, (float*)d_out);
}